// round 4
// baseline (speedup 1.0000x reference)
#include <cuda_runtime.h>
#include <math.h>
#include <stdint.h>

#define TT 4
#define NN 20000
#define EE 320000
#define RR 2
#define DD 64
#define HH 4
#define CC 64
#define HC 256   // H*C
#define ZZ 8     // T*R

typedef unsigned long long ull;

// ----------------- scratch (static device globals; no allocation) -----------------
__device__ __align__(16) float g_agg[ZZ * NN * HC];
__device__ __align__(16) float g_als[ZZ * NN * HH];
__device__ __align__(16) float g_ald[ZZ * NN * HH];
__device__ __align__(16) float g_intra[TT * NN * RR * CC];
__device__ float g_ssum[TT * RR];
__device__ float g_beta[TT * RR];
__device__ __align__(16) float g_inter[TT * NN * CC];
__device__ __align__(16) float g_lh[NN * CC];
__device__ __align__(16) float g_lc[NN * CC];
__device__ __align__(16) float g_feats[NN * TT * CC];
__device__ float g_Wcat[2 * DD * HC];
__device__ float g_folds[RR * DD * HH];
__device__ float g_foldd[RR * DD * HH];
__device__ float g_Bstack[RR * HC * CC];
__device__ int g_cnt[ZZ * NN];
__device__ int g_off[ZZ * (NN + 1)];
__device__ int g_pos[ZZ * NN];
__device__ int g_sorted[ZZ * EE];
__device__ __align__(16) float4 g_wsort[ZZ * EE];

// ----------------- helpers -----------------
__device__ __forceinline__ float sigmoidf_(float x) { return 1.0f / (1.0f + __expf(-x)); }

__device__ __forceinline__ float tanh_approx(float x) {
    float y; asm("tanh.approx.f32 %0, %1;" : "=f"(y) : "f"(x)); return y;
}
__device__ __forceinline__ ull fma2(ull a, ull b, ull c) {
    ull d;
    asm("fma.rn.f32x2 %0, %1, %2, %3;" : "=l"(d) : "l"(a), "l"(b), "l"(c));
    return d;
}
__device__ __forceinline__ ull pack2s(float x) {
    ull u; asm("mov.b64 %0, {%1,%1};" : "=l"(u) : "f"(x)); return u;
}
__device__ __forceinline__ float2 ull2f(ull u) {
    float2 v; asm("mov.b64 {%0,%1}, %2;" : "=f"(v.x), "=f"(v.y) : "l"(u)); return v;
}

// ----------------- prep kernels -----------------
__global__ void fold_att_kernel(const float* __restrict__ Wsrc, const float* __restrict__ Wdst,
                                const float* __restrict__ as_, const float* __restrict__ ad_,
                                float* __restrict__ fs, float* __restrict__ fd) {
    int idx = blockIdx.x * blockDim.x + threadIdx.x;
    if (idx >= RR * DD * HH) return;
    int r = idx / (DD * HH);
    int k = (idx / HH) % DD;
    int h = idx % HH;
    float accs = 0.f, accd = 0.f;
    for (int c = 0; c < CC; ++c) {
        accs += Wsrc[((size_t)(r * DD + k)) * HC + h * CC + c] * as_[(r * HH + h) * CC + c];
        accd += Wdst[((size_t)(r * DD + k)) * HC + h * CC + c] * ad_[(r * HH + h) * CC + c];
    }
    fs[idx] = accs;
    fd[idx] = accd;
}

__global__ void bstack_kernel(const float* __restrict__ Wsrc, float* __restrict__ Bst) {
    int idx = blockIdx.x * blockDim.x + threadIdx.x;
    if (idx >= RR * HC * CC) return;
    int r = idx / (HC * CC);
    int kk = (idx / CC) % HC;
    int co = idx % CC;
    int h = kk >> 6, ci = kk & 63;
    Bst[idx] = Wsrc[((size_t)(r * DD + ci)) * HC + h * 64 + co] * 0.25f;
}

// Wcat[k][g]: k<64 -> Wih[g][k], k>=64 -> Whh[g][k-64]
__global__ void wcat_kernel(const float* __restrict__ Wih, const float* __restrict__ Whh,
                            float* __restrict__ Wcat) {
    int idx = blockIdx.x * blockDim.x + threadIdx.x;
    if (idx >= 2 * DD * HC) return;
    int k = idx >> 8, g = idx & 255;
    Wcat[idx] = (k < 64) ? Wih[g * 64 + k] : Whh[g * 64 + (k - 64)];
}

// ----------------- attention-score projections: one thread per (z,n), 4 heads -------------
__global__ void als_all_kernel(const float* __restrict__ x, const float* __restrict__ fs,
                               const float* __restrict__ fd, float* __restrict__ als,
                               float* __restrict__ ald) {
    int idx = blockIdx.x * blockDim.x + threadIdx.x;
    if (idx >= ZZ * NN) return;
    int z = idx / NN, n = idx - z * NN;
    int t = z >> 1, r = z & 1;
    const float* xr = x + ((size_t)t * NN + n) * DD;
    const float4* fs4 = reinterpret_cast<const float4*>(fs + r * DD * HH);
    const float4* fd4 = reinterpret_cast<const float4*>(fd + r * DD * HH);
    float4 a = {0.f, 0.f, 0.f, 0.f}, b = {0.f, 0.f, 0.f, 0.f};
#pragma unroll 8
    for (int k = 0; k < DD; ++k) {
        float xv = __ldg(xr + k);
        float4 f = __ldg(fs4 + k);
        float4 g = __ldg(fd4 + k);
        a.x += xv * f.x; a.y += xv * f.y; a.z += xv * f.z; a.w += xv * f.w;
        b.x += xv * g.x; b.y += xv * g.y; b.z += xv * g.z; b.w += xv * g.w;
    }
    reinterpret_cast<float4*>(als)[idx] = a;
    reinterpret_cast<float4*>(ald)[idx] = b;
}

// ----------------- CSR build (all 8 z batched) -----------------
__global__ void hist_kernel(const int* __restrict__ ei, int* __restrict__ cnt) {
    int i = blockIdx.x * blockDim.x + threadIdx.x;
    if (i >= ZZ * EE) return;
    int z = i / EE, e = i - z * EE;
    int dst = __ldg(ei + (size_t)z * 2 * EE + EE + e);
    atomicAdd(cnt + z * NN + dst, 1);
}

__global__ __launch_bounds__(1024) void scan_kernel(const int* __restrict__ cnt,
                                                    int* __restrict__ off,
                                                    int* __restrict__ pos) {
    __shared__ int ssums[1024];
    int z = blockIdx.x;
    const int* c = cnt + z * NN;
    int* o = off + z * (NN + 1);
    int* p = pos + z * NN;
    int tid = threadIdx.x;
    const int CH = (NN + 1023) / 1024;  // 20
    int base = tid * CH;
    int s = 0;
    for (int i = 0; i < CH; ++i) {
        int idx = base + i;
        if (idx < NN) s += c[idx];
    }
    ssums[tid] = s;
    __syncthreads();
    for (int d = 1; d < 1024; d <<= 1) {
        int v = (tid >= d) ? ssums[tid - d] : 0;
        __syncthreads();
        ssums[tid] += v;
        __syncthreads();
    }
    int run = (tid > 0) ? ssums[tid - 1] : 0;
    for (int i = 0; i < CH; ++i) {
        int idx = base + i;
        if (idx < NN) {
            o[idx] = run;
            p[idx] = run;
            run += c[idx];
        }
    }
    if (tid == 1023) o[NN] = ssums[1023];
}

// scatter + per-edge softmax weights (4 exps per THREAD -> MUFU pipe off critical path)
__global__ void scatter_kernel(const int* __restrict__ ei, const float* __restrict__ als,
                               const float* __restrict__ ald, int* __restrict__ pos,
                               int* __restrict__ sorted, float4* __restrict__ wsort) {
    int i = blockIdx.x * blockDim.x + threadIdx.x;
    if (i >= ZZ * EE) return;
    int z = i / EE, e = i - z * EE;
    int src = __ldg(ei + (size_t)z * 2 * EE + e);
    int dst = __ldg(ei + (size_t)z * 2 * EE + EE + e);
    float4 s4 = __ldg(reinterpret_cast<const float4*>(als) + (size_t)z * NN + src);
    float4 d4 = __ldg(reinterpret_cast<const float4*>(ald) + (size_t)z * NN + dst);
    float e0 = s4.x + d4.x; e0 = (e0 >= 0.f) ? e0 : 0.2f * e0;
    float e1 = s4.y + d4.y; e1 = (e1 >= 0.f) ? e1 : 0.2f * e1;
    float e2 = s4.z + d4.z; e2 = (e2 >= 0.f) ? e2 : 0.2f * e2;
    float e3 = s4.w + d4.w; e3 = (e3 >= 0.f) ? e3 : 0.2f * e3;
    float4 w = make_float4(__expf(e0), __expf(e1), __expf(e2), __expf(e3));
    int p = atomicAdd(pos + z * NN + dst, 1);
    sorted[(size_t)z * EE + p] = src;
    wsort[(size_t)z * EE + p] = w;
}

// ----------------- gather: warp per (z,dst); pure streaming fma2 -----------------
__global__ __launch_bounds__(256) void gather_kernel(
    const int* __restrict__ off, const int* __restrict__ sorted,
    const float4* __restrict__ wsort, const float* __restrict__ x,
    float* __restrict__ agg) {
    int z = blockIdx.y;
    int d = blockIdx.x * 8 + (threadIdx.x >> 5);
    int lane = threadIdx.x & 31;
    const float* xt = x + (size_t)(z >> 1) * NN * DD;
    const int* offz = off + z * (NN + 1);
    const int* sz = sorted + (size_t)z * EE;
    const float4* wz = wsort + (size_t)z * EE;
    int i = offz[d], iend = offz[d + 1];
    ull A0 = 0ull, A1 = 0ull, A2 = 0ull, A3 = 0ull;
    float d0 = 0.f, d1 = 0.f, d2 = 0.f, d3 = 0.f;
    int src = (i < iend) ? __ldg(sz + i) : 0;
    while (i < iend) {
        float4 w = __ldg(wz + i);
        ull xv = __ldg(reinterpret_cast<const ull*>(xt + (size_t)src * DD) + lane);
        ++i;
        if (i < iend) src = __ldg(sz + i);
        d0 += w.x; d1 += w.y; d2 += w.z; d3 += w.w;
        A0 = fma2(pack2s(w.x), xv, A0);
        A1 = fma2(pack2s(w.y), xv, A1);
        A2 = fma2(pack2s(w.z), xv, A2);
        A3 = fma2(pack2s(w.w), xv, A3);
    }
    float i0 = 1.f / (d0 + 1e-16f), i1 = 1.f / (d1 + 1e-16f);
    float i2 = 1.f / (d2 + 1e-16f), i3 = 1.f / (d3 + 1e-16f);
    float2 a0 = ull2f(A0), a1 = ull2f(A1), a2 = ull2f(A2), a3 = ull2f(A3);
    float2* o = reinterpret_cast<float2*>(agg + ((size_t)z * NN + d) * HC) + lane;
    o[0]  = make_float2(a0.x * i0, a0.y * i0);
    o[32] = make_float2(a1.x * i1, a1.y * i1);
    o[64] = make_float2(a2.x * i2, a2.y * i2);
    o[96] = make_float2(a3.x * i3, a3.y * i3);
}

// ----------------- batched intra GEMM: intra(t,n,r,:) = agg_z @ Bstack_r  (K=256) ----------
__global__ __launch_bounds__(256) void gemm_intra(const float* __restrict__ Abase,
                                                  const float* __restrict__ Bbase,
                                                  float* __restrict__ Cbase) {
    __shared__ float As[64][66];
    __shared__ float Bs[64][66];
    int z = blockIdx.y;
    int t = z >> 1, r = z & 1;
    const float* A = Abase + (size_t)z * NN * HC;
    const float* B = Bbase + (size_t)r * HC * CC;
    float* C = Cbase + (size_t)t * NN * RR * CC + r * CC;
    int tid = threadIdx.x;
    int row0 = blockIdx.x * 64;
    int tx = tid & 15, ty = tid >> 4;
    ull acc2[4][2] = {};
    for (int kc = 0; kc < HC; kc += 64) {
#pragma unroll
        for (int i = 0; i < 16; ++i) {
            int idx = tid + i * 256;
            int rr = idx >> 6, cc = idx & 63;
            As[rr][cc] = (row0 + rr < NN) ? A[(size_t)(row0 + rr) * HC + kc + cc] : 0.f;
            Bs[rr][cc] = B[(size_t)(kc + rr) * CC + cc];
        }
        __syncthreads();
#pragma unroll 16
        for (int k = 0; k < 64; ++k) {
            ull b01 = *reinterpret_cast<const ull*>(&Bs[k][tx * 4]);
            ull b23 = *reinterpret_cast<const ull*>(&Bs[k][tx * 4 + 2]);
#pragma unroll
            for (int m = 0; m < 4; ++m) {
                ull am2 = pack2s(As[ty * 4 + m][k]);
                acc2[m][0] = fma2(am2, b01, acc2[m][0]);
                acc2[m][1] = fma2(am2, b23, acc2[m][1]);
            }
        }
        __syncthreads();
    }
#pragma unroll
    for (int m = 0; m < 4; ++m) {
        int gr = row0 + ty * 4 + m;
        if (gr < NN) {
            float2 lo = ull2f(acc2[m][0]);
            float2 hi = ull2f(acc2[m][1]);
            float* cr = C + (size_t)gr * (RR * CC) + tx * 4;
            cr[0] = lo.x; cr[1] = lo.y; cr[2] = hi.x; cr[3] = hi.y;
        }
    }
}

// ----------------- relation scores: 4 rows per warp iteration -----------------
__global__ __launch_bounds__(256) void relation_kernel(
    const float* __restrict__ hmat, const float* __restrict__ W1,
    const float* __restrict__ b1, const float* __restrict__ W2,
    float* __restrict__ ssum) {
    extern __shared__ float sm[];
    float2* sW1v = reinterpret_cast<float2*>(sm);  // 8192 float2
    float* sb1 = sm + 16384;
    float* sW2 = sm + 16640;
    float* sbins = sm + 16896;
    int tid = threadIdx.x;
    for (int i = tid; i < 8192; i += 256) {
        int k = i >> 7;
        int rem = i & 127;
        int p = rem >> 5, l = rem & 31;
        int j1 = k * 256 + p * 64 + l;
        sW1v[i] = make_float2(W1[j1], W1[j1 + 32]);
    }
    if (tid < 256) { sb1[tid] = b1[tid]; sW2[tid] = W2[tid]; }
    if (tid < TT * RR) sbins[tid] = 0.f;
    __syncthreads();
    int lane = tid & 31;
    int gw = (blockIdx.x * blockDim.x + tid) >> 5;
    int nwarps = (gridDim.x * blockDim.x) >> 5;
    const int groups = (TT * NN * RR) / 4;  // 40000
    const int NR = NN * RR;
    const ull* wbase = reinterpret_cast<const ull*>(sW1v) + lane;
    for (int g = gw; g < groups; g += nwarps) {
        int row = g * 4;
        const float* hr = hmat + (size_t)row * CC;
        float h0[4], h1[4];
#pragma unroll
        for (int j = 0; j < 4; ++j) {
            h0[j] = hr[j * 64 + lane];
            h1[j] = hr[j * 64 + lane + 32];
        }
        ull a2[4][4] = {};
#pragma unroll 4
        for (int k = 0; k < 32; ++k) {
            const ull* w = wbase + k * 128;
            ull w0 = w[0], w1 = w[32], w2 = w[64], w3 = w[96];
#pragma unroll
            for (int j = 0; j < 4; ++j) {
                ull hk2 = pack2s(__shfl_sync(0xffffffffu, h0[j], k));
                a2[j][0] = fma2(hk2, w0, a2[j][0]);
                a2[j][1] = fma2(hk2, w1, a2[j][1]);
                a2[j][2] = fma2(hk2, w2, a2[j][2]);
                a2[j][3] = fma2(hk2, w3, a2[j][3]);
            }
        }
#pragma unroll 4
        for (int k = 0; k < 32; ++k) {
            const ull* w = wbase + (k + 32) * 128;
            ull w0 = w[0], w1 = w[32], w2 = w[64], w3 = w[96];
#pragma unroll
            for (int j = 0; j < 4; ++j) {
                ull hk2 = pack2s(__shfl_sync(0xffffffffu, h1[j], k));
                a2[j][0] = fma2(hk2, w0, a2[j][0]);
                a2[j][1] = fma2(hk2, w1, a2[j][1]);
                a2[j][2] = fma2(hk2, w2, a2[j][2]);
                a2[j][3] = fma2(hk2, w3, a2[j][3]);
            }
        }
        float acc[4];
#pragma unroll
        for (int j = 0; j < 4; ++j) {
            float s = 0.f;
#pragma unroll
            for (int p = 0; p < 4; ++p) {
                float2 av = ull2f(a2[j][p]);
                int j1 = p * 64 + lane, j2 = j1 + 32;
                s += tanh_approx(av.x + sb1[j1]) * sW2[j1];
                s += tanh_approx(av.y + sb1[j2]) * sW2[j2];
            }
            acc[j] = s;
        }
        float accA = acc[0] + acc[2];
        float accB = acc[1] + acc[3];
#pragma unroll
        for (int off2 = 16; off2 > 0; off2 >>= 1) {
            accA += __shfl_down_sync(0xffffffffu, accA, off2);
            accB += __shfl_down_sync(0xffffffffu, accB, off2);
        }
        if (lane == 0) {
            int binb = (row / NR) * RR;
            atomicAdd(&sbins[binb], accA);
            atomicAdd(&sbins[binb + 1], accB);
        }
    }
    __syncthreads();
    if (tid < TT * RR) atomicAdd(&ssum[tid], sbins[tid]);
}

__global__ void beta_kernel(const float* __restrict__ ssum, float* __restrict__ beta) {
    int t = threadIdx.x;
    if (t < TT) {
        float s0 = ssum[t * RR + 0] * (1.0f / NN);
        float s1 = ssum[t * RR + 1] * (1.0f / NN);
        float m = fmaxf(s0, s1);
        float e0 = expf(s0 - m), e1 = expf(s1 - m);
        float inv = 1.f / (e0 + e1);
        beta[t * RR + 0] = e0 * inv;
        beta[t * RR + 1] = e1 * inv;
    }
}

__global__ void inter_kernel(const float* __restrict__ intra, const float* __restrict__ beta,
                             float* __restrict__ inter) {
    int idx = blockIdx.x * blockDim.x + threadIdx.x;
    if (idx >= TT * NN * CC) return;
    int t = idx / (NN * CC);
    size_t nbase = (size_t)(idx / CC) * RR * CC + (idx & 63);
    inter[idx] = beta[t * RR] * intra[nbase] + beta[t * RR + 1] * intra[nbase + CC];
}

// ----------------- fused LSTM step: gates GEMM (K=128) + pointwise, one launch per t -------
// smem: As[64][130] (33KB) + Bs[128][258] (132KB, reused as Gs[64][258] for gate exchange)
#define LSTM_SMEM ((64 * 130 + 128 * 258) * 4)
__global__ __launch_bounds__(256) void lstm_step_kernel(
    const float* __restrict__ inter_t, const float* __restrict__ Wcat,
    const float* __restrict__ bih, const float* __restrict__ bhh,
    float* __restrict__ lh, float* __restrict__ lc, float* __restrict__ feats, int t) {
    extern __shared__ float sm[];
    float* As = sm;                  // 64 x 130
    float* Bs = sm + 64 * 130;       // 128 x 258
    float* Gs = Bs;                  // reuse after compute
    int tid = threadIdx.x;
    int row0 = blockIdx.x * 64;
#pragma unroll
    for (int i = 0; i < 32; ++i) {
        int flat = tid + i * 256;
        int n = flat >> 7, c = flat & 127;
        int gn = row0 + n;
        float v = 0.f;
        if (gn < NN) v = (c < 64) ? inter_t[(size_t)gn * 64 + c] : lh[(size_t)gn * 64 + (c - 64)];
        As[n * 130 + c] = v;
    }
#pragma unroll
    for (int i = 0; i < 128; ++i) {
        int flat = tid + i * 256;
        int k = flat >> 8, g = flat & 255;
        Bs[k * 258 + g] = Wcat[flat];
    }
    __syncthreads();
    int tx = tid & 15, ty = tid >> 4;
    ull acc2[4][8] = {};
#pragma unroll 4
    for (int k = 0; k < 128; ++k) {
        ull b[8];
#pragma unroll
        for (int j = 0; j < 8; ++j)
            b[j] = *reinterpret_cast<const ull*>(&Bs[k * 258 + j * 32 + 2 * tx]);
#pragma unroll
        for (int m = 0; m < 4; ++m) {
            ull a2 = pack2s(As[(ty * 4 + m) * 130 + k]);
#pragma unroll
            for (int j = 0; j < 8; ++j) acc2[m][j] = fma2(a2, b[j], acc2[m][j]);
        }
    }
    __syncthreads();
#pragma unroll
    for (int m = 0; m < 4; ++m)
#pragma unroll
        for (int j = 0; j < 8; ++j)
            *reinterpret_cast<ull*>(&Gs[(ty * 4 + m) * 258 + j * 32 + 2 * tx]) = acc2[m][j];
    __syncthreads();
#pragma unroll
    for (int i = 0; i < 16; ++i) {
        int flat = tid + i * 256;
        int n = flat >> 6, c = flat & 63;
        int gn = row0 + n;
        if (gn < NN) {
            float gi = Gs[n * 258 + c] + bih[c] + bhh[c];
            float gf = Gs[n * 258 + 64 + c] + bih[64 + c] + bhh[64 + c];
            float gg = Gs[n * 258 + 128 + c] + bih[128 + c] + bhh[128 + c];
            float go = Gs[n * 258 + 192 + c] + bih[192 + c] + bhh[192 + c];
            float cprev = lc[(size_t)gn * 64 + c];
            float cc = sigmoidf_(gf) * cprev + sigmoidf_(gi) * tanhf(gg);
            lc[(size_t)gn * 64 + c] = cc;
            float hh = sigmoidf_(go) * tanhf(cc);
            lh[(size_t)gn * 64 + c] = hh;
            feats[((size_t)gn * TT + t) * 64 + c] = hh;
        }
    }
}

// ----------------- temporal multi-head attention: warp per node -----------------
__global__ __launch_bounds__(256) void attn_kernel(
    const float* __restrict__ feats, const float* __restrict__ pos,
    const float* __restrict__ Wq, const float* __restrict__ Wk, const float* __restrict__ Wv,
    float* __restrict__ out) {
    extern __shared__ float sm[];
    float* sWq = sm;
    float* sWk = sm + 4096;
    float* sWv = sm + 8192;
    float* spos = sm + 12288;
    float* wb = sm + 12544;
    int tid = threadIdx.x;
    for (int i = tid; i < 4096; i += 256) {
        sWq[i] = Wq[i]; sWk[i] = Wk[i]; sWv[i] = Wv[i];
    }
    if (tid < 256) spos[tid] = pos[tid];
    __syncthreads();
    int wid = tid >> 5, lane = tid & 31;
    int n = blockIdx.x * 8 + wid;
    if (n >= NN) return;
    float* ti = wb + wid * 1088;
    float* q = ti + 256;
    float* k_ = q + 256;
    float* v = k_ + 256;
    float* a = v + 256;
#pragma unroll
    for (int m = 0; m < 8; ++m) {
        int o = m * 32 + lane;
        ti[o] = feats[(size_t)n * 256 + o] + spos[o];
    }
    __syncwarp();
    {
        const ull* wq64 = reinterpret_cast<const ull*>(sWq);
        const ull* wk64 = reinterpret_cast<const ull*>(sWk);
        const ull* wv64 = reinterpret_cast<const ull*>(sWv);
        ull q2[4] = {}, k2[4] = {}, v2[4] = {};
#pragma unroll 4
        for (int k = 0; k < 64; ++k) {
            ull wq = wq64[k * 32 + lane];
            ull wk = wk64[k * 32 + lane];
            ull wv = wv64[k * 32 + lane];
#pragma unroll
            for (int t = 0; t < 4; ++t) {
                ull tv = pack2s(ti[t * 64 + k]);
                q2[t] = fma2(tv, wq, q2[t]);
                k2[t] = fma2(tv, wk, k2[t]);
                v2[t] = fma2(tv, wv, v2[t]);
            }
        }
#pragma unroll
        for (int t = 0; t < 4; ++t) {
            reinterpret_cast<float2*>(q)[t * 32 + lane] = ull2f(q2[t]);
            reinterpret_cast<float2*>(k_)[t * 32 + lane] = ull2f(k2[t]);
            reinterpret_cast<float2*>(v)[t * 32 + lane] = ull2f(v2[t]);
        }
    }
    __syncwarp();
    if (lane < 16) {
        int h = lane >> 2, tq = lane & 3;
        float sc[4];
        for (int tk = 0; tk <= tq; ++tk) {
            float s = 0.f;
#pragma unroll
            for (int ch = 0; ch < 16; ++ch)
                s += q[tq * 64 + h * 16 + ch] * k_[tk * 64 + h * 16 + ch];
            sc[tk] = s * 0.5f;
        }
        float mx = sc[0];
        for (int tk = 1; tk <= tq; ++tk) mx = fmaxf(mx, sc[tk]);
        float sum = 0.f;
        for (int tk = 0; tk <= tq; ++tk) { sc[tk] = __expf(sc[tk] - mx); sum += sc[tk]; }
        float inv = 1.f / sum;
        for (int tk = 0; tk < 4; ++tk)
            a[h * 16 + tq * 4 + tk] = (tk <= tq) ? sc[tk] * inv : 0.f;
    }
    __syncwarp();
    {
        int h = lane >> 3;
        const ull* v64 = reinterpret_cast<const ull*>(v);
#pragma unroll
        for (int tq = 0; tq < 4; ++tq) {
            ull acc = 0ull;
#pragma unroll
            for (int tk = 0; tk < 4; ++tk)
                acc = fma2(pack2s(a[h * 16 + tq * 4 + tk]), v64[tk * 32 + lane], acc);
            reinterpret_cast<float2*>(out + (size_t)n * 256 + tq * 64)[lane] = ull2f(acc);
        }
    }
}

// ----------------- host launch -----------------
template <typename T>
static T* symaddr(const void* sym) {
    void* p = nullptr;
    cudaGetSymbolAddress(&p, sym);
    return (T*)p;
}

extern "C" void kernel_launch(void* const* d_in, const int* in_sizes, int n_in,
                              void* d_out, int out_size) {
    const float* x = (const float*)d_in[0];
    const int* ei = (const int*)d_in[1];
    const float* W_src = (const float*)d_in[2];
    const float* W_dst = (const float*)d_in[3];
    const float* att_src = (const float*)d_in[4];
    const float* att_dst = (const float*)d_in[5];
    const float* ra_W1 = (const float*)d_in[6];
    const float* ra_b1 = (const float*)d_in[7];
    const float* ra_W2 = (const float*)d_in[8];
    const float* Wih = (const float*)d_in[9];
    const float* Whh = (const float*)d_in[10];
    const float* bih = (const float*)d_in[11];
    const float* bhh = (const float*)d_in[12];
    const float* pos = (const float*)d_in[13];
    const float* Wq = (const float*)d_in[14];
    const float* Wk = (const float*)d_in[15];
    const float* Wv = (const float*)d_in[16];
    float* out = (float*)d_out;

    float* agg = symaddr<float>(g_agg);
    float* als = symaddr<float>(g_als);
    float* ald = symaddr<float>(g_ald);
    float* intra = symaddr<float>(g_intra);
    float* ssum = symaddr<float>(g_ssum);
    float* beta = symaddr<float>(g_beta);
    float* inter = symaddr<float>(g_inter);
    float* lh = symaddr<float>(g_lh);
    float* lc = symaddr<float>(g_lc);
    float* feats = symaddr<float>(g_feats);
    float* Wcat = symaddr<float>(g_Wcat);
    float* folds = symaddr<float>(g_folds);
    float* foldd = symaddr<float>(g_foldd);
    float* Bstack = symaddr<float>(g_Bstack);
    int* cnt = symaddr<int>(g_cnt);
    int* off = symaddr<int>(g_off);
    int* posb = symaddr<int>(g_pos);
    int* sorted = symaddr<int>(g_sorted);
    float4* wsort = symaddr<float4>(g_wsort);

    const int REL_SMEM = (16384 + 256 + 256 + 8) * 4;
    const int ATT_SMEM = (12544 + 8 * 1088) * 4;
    cudaFuncSetAttribute(relation_kernel, cudaFuncAttributeMaxDynamicSharedMemorySize, REL_SMEM);
    cudaFuncSetAttribute(attn_kernel, cudaFuncAttributeMaxDynamicSharedMemorySize, ATT_SMEM);
    cudaFuncSetAttribute(lstm_step_kernel, cudaFuncAttributeMaxDynamicSharedMemorySize, LSTM_SMEM);

    // ---- CSR + GAT front (ordered so ncu -s 5 lands on scatter/gather)
    cudaMemsetAsync(cnt, 0, (size_t)ZZ * NN * sizeof(int), 0);
    hist_kernel<<<(ZZ * EE) / 256, 256>>>(ei, cnt);
    scan_kernel<<<ZZ, 1024>>>(cnt, off, posb);
    fold_att_kernel<<<2, 256>>>(W_src, W_dst, att_src, att_dst, folds, foldd);
    als_all_kernel<<<(ZZ * NN + 255) / 256, 256>>>(x, folds, foldd, als, ald);
    scatter_kernel<<<(ZZ * EE) / 256, 256>>>(ei, als, ald, posb, sorted, wsort);
    gather_kernel<<<dim3(NN / 8, ZZ), 256>>>(off, sorted, wsort, x, agg);

    // ---- batched intra GEMM
    bstack_kernel<<<128, 256>>>(W_src, Bstack);
    gemm_intra<<<dim3((NN + 63) / 64, ZZ), 256>>>(agg, Bstack, intra);

    // ---- relation aggregation
    cudaMemsetAsync(ssum, 0, TT * RR * sizeof(float), 0);
    relation_kernel<<<444, 256, REL_SMEM>>>(intra, ra_W1, ra_b1, ra_W2, ssum);
    beta_kernel<<<1, 32>>>(ssum, beta);
    inter_kernel<<<(TT * NN * CC + 255) / 256, 256>>>(intra, beta, inter);

    // ---- LSTM (fused gemm+pointwise per step)
    wcat_kernel<<<128, 256>>>(Wih, Whh, Wcat);
    cudaMemsetAsync(lh, 0, (size_t)NN * CC * sizeof(float), 0);
    cudaMemsetAsync(lc, 0, (size_t)NN * CC * sizeof(float), 0);
    for (int t = 0; t < TT; ++t) {
        lstm_step_kernel<<<(NN + 63) / 64, 256, LSTM_SMEM>>>(
            inter + (size_t)t * NN * CC, Wcat, bih, bhh, lh, lc, feats, t);
    }

    // ---- temporal attention
    attn_kernel<<<(NN + 7) / 8, 256, ATT_SMEM>>>(feats, pos, Wq, Wk, Wv, out);
}